// round 8
// baseline (speedup 1.0000x reference)
#include <cuda_runtime.h>
#include <cuda_bf16.h>
#include <cstdint>

#define BB 256
#define TT 20
#define HH 512
#define WVV 301
#define FF 196
#define CC 512
#define VV 9871
#define XK 813
#define NAG 708

#define KSEC 832          // padded K section (>=813, mult of 64)
#define LKP 2496          // 3 * KSEC

#define KP 1536           // vocab split K = 3*512
#define NPAD 9984
#define MROWS (TT * BB)   // 5120

// ---------------- device globals ------------------------------------------------
__device__ __nv_bfloat16 g_Aattn[(size_t)TT * BB * LKP];  // [x|h] hi/hi/lo triple
__device__ __nv_bfloat16 g_Acomb[(size_t)TT * BB * LKP];  // [x|ctx]
__device__ __nv_bfloat16 g_Aih[(size_t)BB * LKP];         // [inp|h]
__device__ __nv_bfloat16 g_Wag2[(size_t)768 * LKP];       // [Whi|Wlo|Whi]
__device__ __nv_bfloat16 g_Wcomb2[(size_t)320 * LKP];
__device__ __nv_bfloat16 g_Wl2[(size_t)2048 * LKP];
__device__ float g_ag_s[3 * BB * 768];   // attn+gate logit slices (split-K x3)
__device__ float g_gates[BB * 2048];     // lstm gate preacts
__device__ float g_cst[BB * HH];         // cell state
__device__ float g_bl[2048];             // bih + bhh
__device__ __nv_bfloat16 g_ap[(size_t)MROWS * KP];  // vocab A'' [hi|hi|lo]
__device__ __nv_bfloat16 g_wp[(size_t)NPAD * KP];   // vocab W'' [hi|lo|hi]

// ---------------- common helpers ------------------------------------------------
__device__ __forceinline__ uint32_t smem_u32(const void* p) {
    uint32_t a;
    asm("{ .reg .u64 t; cvta.to.shared.u64 t, %1; cvt.u32.u64 %0, t; }" : "=r"(a) : "l"(p));
    return a;
}
__device__ __forceinline__ void cp16(uint32_t saddr, const void* gptr) {
    asm volatile("cp.async.cg.shared.global [%0], [%1], 16;" :: "r"(saddr), "l"(gptr));
}
__device__ __forceinline__ void cp_commit() { asm volatile("cp.async.commit_group;"); }
template <int N>
__device__ __forceinline__ void cp_wait() { asm volatile("cp.async.wait_group %0;" :: "n"(N)); }
__device__ __forceinline__ void ldm_x4(uint32_t* r, uint32_t addr) {
    asm volatile("ldmatrix.sync.aligned.m8n8.x4.shared.b16 {%0,%1,%2,%3}, [%4];"
                 : "=r"(r[0]), "=r"(r[1]), "=r"(r[2]), "=r"(r[3]) : "r"(addr));
}
__device__ __forceinline__ void mma_bf16(float* c, const uint32_t* a, uint32_t b0, uint32_t b1) {
    asm volatile(
        "mma.sync.aligned.m16n8k16.row.col.f32.bf16.bf16.f32 "
        "{%0,%1,%2,%3}, {%4,%5,%6,%7}, {%8,%9}, {%0,%1,%2,%3};"
        : "+f"(c[0]), "+f"(c[1]), "+f"(c[2]), "+f"(c[3])
        : "r"(a[0]), "r"(a[1]), "r"(a[2]), "r"(a[3]), "r"(b0), "r"(b1));
}
// 64B-row swizzle (vocab gemm, BK=32 tiles)
__device__ __forceinline__ uint32_t swz(int row, int c) {
    return (uint32_t)(row * 64 + ((c ^ ((row >> 1) & 3)) * 16));
}
// 128B-row swizzle (loop gemm, BK=64 tiles): 8 chunks/row, XOR by row&7
__device__ __forceinline__ uint32_t swz128(int row, int c) {
    return (uint32_t)(row * 128 + ((c ^ (row & 7)) * 16));
}
__device__ __forceinline__ void split_bf16(float v, __nv_bfloat16& hi, __nv_bfloat16& lo) {
    hi = __float2bfloat16(v);
    lo = __float2bfloat16(v - __bfloat162float(hi));
}

// 64x64 tile bf16 GEMM, BK=64 per iteration, 3-stage cp.async pipeline.
// stage = A(8KB) + B(8KB) = 16KB. blockDim = 256 (8 warps: 4m x 2n of 16x32).
template <int NIT>
__device__ __forceinline__ void tile_mma64(const __nv_bfloat16* __restrict__ Ag,
                                           const __nv_bfloat16* __restrict__ Bg,
                                           int bm, int bn, int koff, char* spipe,
                                           float acc[4][4]) {
    uint32_t smb = smem_u32(spipe);
    int tid = threadIdx.x;
    int wid = tid >> 5, lane = tid & 31;
    int wm = wid & 3, wn = wid >> 2;
    int a_r = lane & 15, a_c = lane >> 4;
    int b_r = (lane & 7) | (((lane >> 4) & 1) << 3);
    int b_c = (lane >> 3) & 1;
#pragma unroll
    for (int q = 0; q < 4; q++)
#pragma unroll
        for (int j = 0; j < 4; j++) acc[q][j] = 0.f;

    // loader geometry: chunk idx in [0,512): row = idx>>3, c = idx&7; 2 chunks/thread
    int r0c = tid >> 3, c0c = tid & 7;           // idx = tid
    int r1c = (tid + 256) >> 3, c1c = tid & 7;   // idx = tid + 256

#pragma unroll
    for (int st = 0; st < 2; st++) {
        if (st < NIT) {
            uint32_t ab = smb + st * 16384;
            int kbase = koff + st * 64;
            cp16(ab + swz128(r0c, c0c), Ag + (size_t)(bm + r0c) * LKP + kbase + c0c * 8);
            cp16(ab + swz128(r1c, c1c), Ag + (size_t)(bm + r1c) * LKP + kbase + c1c * 8);
            cp16(ab + 8192 + swz128(r0c, c0c), Bg + (size_t)(bn + r0c) * LKP + kbase + c0c * 8);
            cp16(ab + 8192 + swz128(r1c, c1c), Bg + (size_t)(bn + r1c) * LKP + kbase + c1c * 8);
        }
        cp_commit();
    }
    for (int kt = 0; kt < NIT; kt++) {
        cp_wait<1>();
        __syncthreads();
        int nx = kt + 2;
        if (nx < NIT) {
            uint32_t ab = smb + (nx % 3) * 16384;
            int kbase = koff + nx * 64;
            cp16(ab + swz128(r0c, c0c), Ag + (size_t)(bm + r0c) * LKP + kbase + c0c * 8);
            cp16(ab + swz128(r1c, c1c), Ag + (size_t)(bm + r1c) * LKP + kbase + c1c * 8);
            cp16(ab + 8192 + swz128(r0c, c0c), Bg + (size_t)(bn + r0c) * LKP + kbase + c0c * 8);
            cp16(ab + 8192 + swz128(r1c, c1c), Bg + (size_t)(bn + r1c) * LKP + kbase + c1c * 8);
        }
        cp_commit();
        uint32_t ab = smb + (kt % 3) * 16384;
        uint32_t bb = ab + 8192;
#pragma unroll
        for (int s = 0; s < 4; s++) {
            uint32_t af[4];
            ldm_x4(af, ab + swz128(wm * 16 + a_r, s * 2 + a_c));
#pragma unroll
            for (int jj = 0; jj < 2; jj++) {
                uint32_t bf[4];
                ldm_x4(bf, bb + swz128(wn * 32 + jj * 16 + b_r, s * 2 + b_c));
                mma_bf16(acc[2 * jj], af, bf[0], bf[1]);
                mma_bf16(acc[2 * jj + 1], af, bf[2], bf[3]);
            }
        }
        __syncthreads();
    }
}

#define PIPE_SMEM (3 * 16384)   // 48KB

// ---------------- setup kernels (3 launches before loop) ------------------------
__global__ void zero_all_kernel() {
    size_t stride = (size_t)gridDim.x * blockDim.x;
    size_t id = (size_t)blockIdx.x * blockDim.x + threadIdx.x;
    uint4 z = make_uint4(0, 0, 0, 0);
    uint4* pa = (uint4*)g_Aattn;
    size_t nA = sizeof(g_Aattn) / 16;
    for (size_t i = id; i < nA; i += stride) pa[i] = z;
    uint4* pc = (uint4*)g_Acomb;
    for (size_t i = id; i < nA; i += stride) pc[i] = z;
    uint4* pi = (uint4*)g_Aih;
    size_t nI = sizeof(g_Aih) / 16;
    for (size_t i = id; i < nI; i += stride) pi[i] = z;
    uint4* ps = (uint4*)g_cst;
    size_t nS = sizeof(g_cst) / 16;
    for (size_t i = id; i < nS; i += stride) ps[i] = z;
}

__global__ void setup_x2_kernel(const float* __restrict__ wv) {
    int idx = blockIdx.x * blockDim.x + threadIdx.x;
    const int total = TT * BB * WVV;
    if (idx >= total) return;
    int t = idx / (BB * WVV);
    int r = idx % (BB * WVV);
    int b = r / WVV, w = r % WVV;
    float v = (t == 0) ? 0.f : wv[(size_t)b * TT * WVV + (size_t)(t - 1) * WVV + w];
    __nv_bfloat16 hi, lo;
    split_bf16(v, hi, lo);
    size_t base = ((size_t)t * BB + b) * LKP;
    g_Aattn[base + w] = hi;
    g_Aattn[base + KSEC + w] = hi;
    g_Aattn[base + 2 * KSEC + w] = lo;
    g_Acomb[base + w] = hi;
    g_Acomb[base + KSEC + w] = hi;
    g_Acomb[base + 2 * KSEC + w] = lo;
}

// merged weight prep: wag2 | wcomb2 | wl2 | wp | bl
#define NW0 (768 * KSEC)
#define NW1 (320 * KSEC)
#define NW2 (2048 * KSEC)
#define NW3 (NPAD * HH)
__global__ void setup_weights_kernel(const float* __restrict__ attn_W,
                                     const float* __restrict__ gate_W,
                                     const float* __restrict__ comb_W,
                                     const float* __restrict__ Wih,
                                     const float* __restrict__ Whh,
                                     const float* __restrict__ bih,
                                     const float* __restrict__ bhh,
                                     const float* __restrict__ vw) {
    long idx = (long)blockIdx.x * blockDim.x + threadIdx.x;
    if (idx < 2048) g_bl[idx] = bih[idx] + bhh[idx];
    if (idx < NW0) {
        int n = idx / KSEC, k = idx % KSEC;
        float v = 0.f;
        if (k < XK) {
            if (n < FF) v = attn_W[(size_t)n * XK + k];
            else if (n < NAG && k >= WVV) v = gate_W[(size_t)(n - FF) * HH + (k - WVV)];
        }
        __nv_bfloat16 hi, lo;
        split_bf16(v, hi, lo);
        size_t base = (size_t)n * LKP;
        g_Wag2[base + k] = hi;
        g_Wag2[base + KSEC + k] = lo;
        g_Wag2[base + 2 * KSEC + k] = hi;
        return;
    }
    idx -= NW0;
    if (idx < NW1) {
        int n = idx / KSEC, k = idx % KSEC;
        float v = (n < WVV && k < XK) ? comb_W[(size_t)n * XK + k] : 0.f;
        __nv_bfloat16 hi, lo;
        split_bf16(v, hi, lo);
        size_t base = (size_t)n * LKP;
        g_Wcomb2[base + k] = hi;
        g_Wcomb2[base + KSEC + k] = lo;
        g_Wcomb2[base + 2 * KSEC + k] = hi;
        return;
    }
    idx -= NW1;
    if (idx < NW2) {
        int n = idx / KSEC, k = idx % KSEC;
        float v = 0.f;
        if (k < XK) v = (k < WVV) ? Wih[(size_t)n * WVV + k] : Whh[(size_t)n * HH + (k - WVV)];
        __nv_bfloat16 hi, lo;
        split_bf16(v, hi, lo);
        size_t base = (size_t)n * LKP;
        g_Wl2[base + k] = hi;
        g_Wl2[base + KSEC + k] = lo;
        g_Wl2[base + 2 * KSEC + k] = hi;
        return;
    }
    idx -= NW2;
    if (idx < NW3) {
        int n = idx / HH, k = idx % HH;
        float v = (n < VV) ? vw[(size_t)n * HH + k] : 0.f;
        __nv_bfloat16 hi, lo;
        split_bf16(v, hi, lo);
        size_t base = (size_t)n * KP;
        g_wp[base + k] = hi;
        g_wp[base + HH + k] = lo;
        g_wp[base + 2 * HH + k] = hi;
    }
}

// ---------------- loop kernels (5 launches per step) ----------------------------
// P1: attn+gate logits, split-K x3. grid = 144
__global__ void __launch_bounds__(256, 1) k_p1(const __nv_bfloat16* __restrict__ A) {
    extern __shared__ __align__(16) char s_pipe[];
    float acc[4][4];
    int job = blockIdx.x;
    int z = job % 3, tile = job / 3;
    int bm = (tile / 12) * 64, bn = (tile % 12) * 64;
    tile_mma64<13>(A, g_Wag2, bm, bn, z * KSEC, s_pipe, acc);
    int tid = threadIdx.x, wid = tid >> 5, lane = tid & 31;
    float* dst = g_ag_s + (size_t)z * BB * 768;
    int r0 = bm + (wid & 3) * 16 + (lane >> 2);
    int c0 = bn + (wid >> 2) * 32 + 2 * (lane & 3);
#pragma unroll
    for (int q = 0; q < 4; q++)
#pragma unroll
        for (int h = 0; h < 2; h++) {
            dst[(r0 + 8 * h) * 768 + c0 + q * 8] = acc[q][2 * h];
            dst[(r0 + 8 * h) * 768 + c0 + q * 8 + 1] = acc[q][2 * h + 1];
        }
}

// P2: softmax + gated ctx. grid = BB (one block per b)
__global__ void __launch_bounds__(256, 1)
k_p2(const float* __restrict__ enc, const float* __restrict__ attn_b,
     const float* __restrict__ gate_b, __nv_bfloat16* __restrict__ Acomb_t) {
    __shared__ float s_red[256];
    __shared__ __align__(16) float s_aw[196];
    int b = blockIdx.x;
    int tid = threadIdx.x;
    int wid = tid >> 5, lane = tid & 31;
    const float* p0 = g_ag_s + (size_t)b * 768;
    const float* p1 = p0 + (size_t)BB * 768;
    const float* p2 = p1 + (size_t)BB * 768;
    float v = -3.0e38f;
    if (tid < FF) v = attn_b[tid] + p0[tid] + p1[tid] + p2[tid];
    s_red[tid] = v;
    __syncthreads();
    for (int s = 128; s > 0; s >>= 1) {
        if (tid < s) s_red[tid] = fmaxf(s_red[tid], s_red[tid + s]);
        __syncthreads();
    }
    float mx = s_red[0];
    __syncthreads();
    float e = (tid < FF) ? expf(v - mx) : 0.f;
    s_red[tid] = e;
    __syncthreads();
    for (int s = 128; s > 0; s >>= 1) {
        if (tid < s) s_red[tid] += s_red[tid + s];
        __syncthreads();
    }
    float inv = 1.f / s_red[0];
    __syncthreads();
    if (tid < FF) s_aw[tid] = e * inv;
    __syncthreads();
    const float4* sa4 = (const float4*)s_aw;
    const float4* encb = (const float4*)(enc + (size_t)b * CC * FF);
    size_t cbase = (size_t)b * LKP;
    for (int grp = 0; grp < 8; grp++) {
#pragma unroll
        for (int ci = 0; ci < 8; ci++) {
            int c = wid * 64 + grp * 8 + ci;
            const float4* row = encb + (size_t)c * 49;
            float4 a0 = sa4[lane];
            float4 v0 = row[lane];
            float sum = v0.x * a0.x + v0.y * a0.y + v0.z * a0.z + v0.w * a0.w;
            if (lane < 17) {
                float4 a1 = sa4[lane + 32];
                float4 v1 = row[lane + 32];
                sum += v1.x * a1.x + v1.y * a1.y + v1.z * a1.z + v1.w * a1.w;
            }
#pragma unroll
            for (int o = 16; o > 0; o >>= 1) sum += __shfl_xor_sync(0xffffffffu, sum, o);
            if (lane == 0) {
                float gz = gate_b[c] + p0[FF + c] + p1[FF + c] + p2[FF + c];
                float gamma = 1.f / (1.f + expf(-gz));
                float val = gamma * sum;
                __nv_bfloat16 hi, lo;
                split_bf16(val, hi, lo);
                Acomb_t[cbase + WVV + c] = hi;
                Acomb_t[cbase + KSEC + WVV + c] = hi;
                Acomb_t[cbase + 2 * KSEC + WVV + c] = lo;
            }
        }
    }
}

// P3: comb gemm full-K, relu fused in epilogue -> g_Aih triple. grid = 20
__global__ void __launch_bounds__(256, 1)
k_p3(const __nv_bfloat16* __restrict__ A, const float* __restrict__ comb_b) {
    extern __shared__ __align__(16) char s_pipe[];
    float acc[4][4];
    int job = blockIdx.x;
    int bm = (job / 5) * 64, bn = (job % 5) * 64;
    tile_mma64<39>(A, g_Wcomb2, bm, bn, 0, s_pipe, acc);
    int tid = threadIdx.x, wid = tid >> 5, lane = tid & 31;
    int r0 = bm + (wid & 3) * 16 + (lane >> 2);
    int c0 = bn + (wid >> 2) * 32 + 2 * (lane & 3);
#pragma unroll
    for (int q = 0; q < 4; q++)
#pragma unroll
        for (int h = 0; h < 2; h++) {
            int gm = r0 + 8 * h;
            size_t abase = (size_t)gm * LKP;
#pragma unroll
            for (int u = 0; u < 2; u++) {
                int n = c0 + q * 8 + u;
                if (n < WVV) {
                    float val = fmaxf(acc[q][2 * h + u] + comb_b[n], 0.f);
                    __nv_bfloat16 hi, lo;
                    split_bf16(val, hi, lo);
                    g_Aih[abase + n] = hi;
                    g_Aih[abase + KSEC + n] = hi;
                    g_Aih[abase + 2 * KSEC + n] = lo;
                }
            }
        }
}

// P4: lstm gates gemm full-K -> g_gates. grid = 128
__global__ void __launch_bounds__(256, 1) k_p4() {
    extern __shared__ __align__(16) char s_pipe[];
    float acc[4][4];
    int job = blockIdx.x;
    int bm = (job / 32) * 64, bn = (job % 32) * 64;
    tile_mma64<39>(g_Aih, g_Wl2, bm, bn, 0, s_pipe, acc);
    int tid = threadIdx.x, wid = tid >> 5, lane = tid & 31;
    int r0 = bm + (wid & 3) * 16 + (lane >> 2);
    int c0 = bn + (wid >> 2) * 32 + 2 * (lane & 3);
#pragma unroll
    for (int q = 0; q < 4; q++)
#pragma unroll
        for (int h = 0; h < 2; h++) {
            g_gates[(r0 + 8 * h) * 2048 + c0 + q * 8] = acc[q][2 * h];
            g_gates[(r0 + 8 * h) * 2048 + c0 + q * 8 + 1] = acc[q][2 * h + 1];
        }
}

// P5: LSTM cell elementwise. grid = BB*HH/256 = 512
__global__ void __launch_bounds__(256, 1)
k_p5(int t, __nv_bfloat16* __restrict__ Aattn_next) {
    int idx = blockIdx.x * 256 + threadIdx.x;
    int b = idx >> 9, j = idx & 511;
    const float* gr = g_gates + b * 2048;
    float i_ = gr[j] + g_bl[j];
    float f_ = gr[512 + j] + g_bl[512 + j];
    float g_ = gr[1024 + j] + g_bl[1024 + j];
    float o_ = gr[1536 + j] + g_bl[1536 + j];
    float si = 1.f / (1.f + expf(-i_));
    float sf = 1.f / (1.f + expf(-f_));
    float so = 1.f / (1.f + expf(-o_));
    float cn = sf * g_cst[idx] + si * tanhf(g_);
    float hn = so * tanhf(cn);
    g_cst[idx] = cn;
    __nv_bfloat16 hi, lo;
    split_bf16(hn, hi, lo);
    size_t ib = (size_t)b * LKP + WVV + j;
    g_Aih[ib] = hi;
    g_Aih[ib + KSEC] = hi;
    g_Aih[ib + 2 * KSEC] = lo;
    if (Aattn_next) {
        size_t ab = (size_t)b * LKP + WVV + j;
        Aattn_next[ab] = hi;
        Aattn_next[ab + KSEC] = hi;
        Aattn_next[ab + 2 * KSEC] = lo;
    }
    size_t vb = ((size_t)t * BB + b) * KP;
    g_ap[vb + j] = hi;
    g_ap[vb + HH + j] = hi;
    g_ap[vb + 2 * HH + j] = lo;
}

// ===================== vocab GEMM (unchanged, known good) =======================
#define VBM 128
#define VBN 256
#define NKT (KP / 32)      // 48
#define STAGE_BYTES 24576
#define ASZ 8192
#define NSTAGE 3
#define VSMEM (NSTAGE * STAGE_BYTES)

__device__ __forceinline__ void issue_tile(const __nv_bfloat16* __restrict__ Ag,
                                           const __nv_bfloat16* __restrict__ Bg,
                                           uint32_t smb, int stage, int bm, int bn, int kt) {
    int tid = threadIdx.x;
    uint32_t abase = smb + stage * STAGE_BYTES;
    uint32_t bbase = abase + ASZ;
#pragma unroll
    for (int l = 0; l < 2; l++) {
        int idx = tid + 256 * l;
        int row = idx >> 2, c = idx & 3;
        cp16(abase + swz(row, c), Ag + (size_t)(bm + row) * KP + kt * 32 + c * 8);
    }
#pragma unroll
    for (int l = 0; l < 4; l++) {
        int idx = tid + 256 * l;
        int row = idx >> 2, c = idx & 3;
        cp16(bbase + swz(row, c), Bg + (size_t)(bn + row) * KP + kt * 32 + c * 8);
    }
    cp_commit();
}

__global__ void __launch_bounds__(256, 1)
gemm_vocab_mma(const __nv_bfloat16* __restrict__ Ag, const __nv_bfloat16* __restrict__ Bg,
               const float* __restrict__ bias, float* __restrict__ out) {
    extern __shared__ char sm[];
    uint32_t smb = smem_u32(sm);
    int tid = threadIdx.x;
    int wid = tid >> 5, lane = tid & 31;
    int wm = wid & 1, wn = wid >> 1;
    int bm = blockIdx.y * VBM, bn = blockIdx.x * VBN;

    int a_r = lane & 15;
    int a_c = lane >> 4;
    int b_r = (lane & 7) | (((lane >> 4) & 1) << 3);
    int b_c = (lane >> 3) & 1;

    float acc[4][8][4];
#pragma unroll
    for (int i = 0; i < 4; i++)
#pragma unroll
        for (int j = 0; j < 8; j++)
#pragma unroll
            for (int q = 0; q < 4; q++) acc[i][j][q] = 0.f;

    issue_tile(Ag, Bg, smb, 0, bm, bn, 0);
    issue_tile(Ag, Bg, smb, 1, bm, bn, 1);

    for (int kt = 0; kt < NKT; kt++) {
        cp_wait<1>();
        __syncthreads();
        if (kt + 2 < NKT) issue_tile(Ag, Bg, smb, (kt + 2) % NSTAGE, bm, bn, kt + 2);
        uint32_t abase = smb + (kt % NSTAGE) * STAGE_BYTES;
        uint32_t bbase = abase + ASZ;
#pragma unroll
        for (int s = 0; s < 2; s++) {
            uint32_t af[4][4], bf[4][4];
#pragma unroll
            for (int i = 0; i < 4; i++) {
                int row = wm * 64 + i * 16 + a_r;
                ldm_x4(af[i], abase + swz(row, s * 2 + a_c));
            }
#pragma unroll
            for (int jj = 0; jj < 4; jj++) {
                int row = wn * 64 + jj * 16 + b_r;
                ldm_x4(bf[jj], bbase + swz(row, s * 2 + b_c));
            }
#pragma unroll
            for (int i = 0; i < 4; i++)
#pragma unroll
                for (int jj = 0; jj < 4; jj++) {
                    mma_bf16(acc[i][2 * jj], af[i], bf[jj][0], bf[jj][1]);
                    mma_bf16(acc[i][2 * jj + 1], af[i], bf[jj][2], bf[jj][3]);
                }
        }
        __syncthreads();
    }

#pragma unroll
    for (int i = 0; i < 4; i++) {
#pragma unroll
        for (int j = 0; j < 8; j++) {
            int gm0 = bm + wm * 64 + i * 16 + (lane >> 2);
            int gn = bn + wn * 64 + j * 8 + 2 * (lane & 3);
#pragma unroll
            for (int h = 0; h < 2; h++) {
                int gm = gm0 + h * 8;
                int t = gm >> 8, b = gm & 255;
                float* row = out + ((size_t)b * TT + t) * VV;
                float c0 = acc[i][j][2 * h], c1 = acc[i][j][2 * h + 1];
                if (gn < VV) row[gn] = c0 + bias[gn];
                if (gn + 1 < VV) row[gn + 1] = c1 + bias[gn + 1];
            }
        }
    }
}

// ---------------- host launch --------------------------------------------------
extern "C" void kernel_launch(void* const* d_in, const int* in_sizes, int n_in,
                              void* d_out, int out_size) {
    const float* enc     = (const float*)d_in[0];
    const float* wv      = (const float*)d_in[1];
    const float* attn_W  = (const float*)d_in[2];
    const float* attn_b  = (const float*)d_in[3];
    const float* comb_W  = (const float*)d_in[4];
    const float* comb_b  = (const float*)d_in[5];
    const float* gate_W  = (const float*)d_in[6];
    const float* gate_b  = (const float*)d_in[7];
    const float* Wih     = (const float*)d_in[8];
    const float* Whh     = (const float*)d_in[9];
    const float* bih     = (const float*)d_in[10];
    const float* bhh     = (const float*)d_in[11];
    const float* vocab_W = (const float*)d_in[12];
    const float* vocab_b = (const float*)d_in[13];
    float* out = (float*)d_out;

    __nv_bfloat16 *p_Aattn, *p_Acomb, *p_ap, *p_wp;
    cudaGetSymbolAddress((void**)&p_Aattn, g_Aattn);
    cudaGetSymbolAddress((void**)&p_Acomb, g_Acomb);
    cudaGetSymbolAddress((void**)&p_ap, g_ap);
    cudaGetSymbolAddress((void**)&p_wp, g_wp);

    cudaFuncSetAttribute(gemm_vocab_mma, cudaFuncAttributeMaxDynamicSharedMemorySize, VSMEM);
    cudaFuncSetAttribute(k_p1, cudaFuncAttributeMaxDynamicSharedMemorySize, PIPE_SMEM);
    cudaFuncSetAttribute(k_p3, cudaFuncAttributeMaxDynamicSharedMemorySize, PIPE_SMEM);
    cudaFuncSetAttribute(k_p4, cudaFuncAttributeMaxDynamicSharedMemorySize, PIPE_SMEM);

    zero_all_kernel<<<1024, 256>>>();
    setup_x2_kernel<<<(TT * BB * WVV + 255) / 256, 256>>>(wv);
    {
        long total = (long)NW0 + NW1 + NW2 + NW3;
        setup_weights_kernel<<<(unsigned)((total + 255) / 256), 256>>>(
            attn_W, gate_W, comb_W, Wih, Whh, bih, bhh, vocab_W);
    }

    for (int t = 0; t < TT; t++) {
        const __nv_bfloat16* Aat = p_Aattn + (size_t)t * BB * LKP;
        __nv_bfloat16* Aco = p_Acomb + (size_t)t * BB * LKP;
        k_p1<<<144, 256, PIPE_SMEM>>>(Aat);
        k_p2<<<BB, 256>>>(enc, attn_b, gate_b, Aco);
        k_p3<<<20, 256, PIPE_SMEM>>>(Aco, comb_b);
        k_p4<<<128, 256, PIPE_SMEM>>>();
        __nv_bfloat16* Anext = (t + 1 < TT) ? (p_Aattn + (size_t)(t + 1) * BB * LKP) : (__nv_bfloat16*)nullptr;
        k_p5<<<512, 256>>>(t, Anext);
    }
    gemm_vocab_mma<<<dim3(NPAD / VBN, MROWS / VBM), 256, VSMEM>>>(p_ap, p_wp, vocab_b, out);
}

// round 9
// speedup vs baseline: 1.2094x; 1.2094x over previous
#include <cuda_runtime.h>
#include <cuda_bf16.h>
#include <cstdint>

#define BB 256
#define TT 20
#define HH 512
#define WVV 301
#define FF 196
#define CC 512
#define VV 9871
#define XK 813
#define NAG 708

#define KSEC 832          // padded K section (>=813, mult of 32)
#define LKP 2496          // 3 * KSEC

#define KP 1536           // vocab split K = 3*512
#define NPAD 9984
#define MROWS (TT * BB)   // 5120

// ---------------- device globals ------------------------------------------------
__device__ __nv_bfloat16 g_Aattn[(size_t)TT * BB * LKP];  // [x|h] hi/hi/lo triple
__device__ __nv_bfloat16 g_Acomb[(size_t)TT * BB * LKP];  // [x|ctx]
__device__ __nv_bfloat16 g_Aih[(size_t)BB * LKP];         // [inp|h]
__device__ __nv_bfloat16 g_Wag2[(size_t)768 * LKP];       // [Whi|Wlo|Whi]
__device__ __nv_bfloat16 g_Wcomb2[(size_t)320 * LKP];
__device__ __nv_bfloat16 g_Wl2[(size_t)2048 * LKP];
__device__ float g_ag_s[3 * BB * 768];   // attn+gate logit slices (split-K x3)
__device__ float g_gates[BB * 2048];     // lstm gate preacts
__device__ float g_cst[BB * HH];         // cell state
__device__ float g_bl[2048];             // bih + bhh
__device__ __nv_bfloat16 g_ap[(size_t)MROWS * KP];  // vocab A'' [hi|hi|lo]
__device__ __nv_bfloat16 g_wp[(size_t)NPAD * KP];   // vocab W'' [hi|lo|hi]

// ---------------- common helpers ------------------------------------------------
__device__ __forceinline__ uint32_t smem_u32(const void* p) {
    uint32_t a;
    asm("{ .reg .u64 t; cvta.to.shared.u64 t, %1; cvt.u32.u64 %0, t; }" : "=r"(a) : "l"(p));
    return a;
}
__device__ __forceinline__ void cp16(uint32_t saddr, const void* gptr) {
    asm volatile("cp.async.cg.shared.global [%0], [%1], 16;" :: "r"(saddr), "l"(gptr));
}
__device__ __forceinline__ void cp_commit() { asm volatile("cp.async.commit_group;"); }
template <int N>
__device__ __forceinline__ void cp_wait() { asm volatile("cp.async.wait_group %0;" :: "n"(N)); }
__device__ __forceinline__ void ldm_x4(uint32_t* r, uint32_t addr) {
    asm volatile("ldmatrix.sync.aligned.m8n8.x4.shared.b16 {%0,%1,%2,%3}, [%4];"
                 : "=r"(r[0]), "=r"(r[1]), "=r"(r[2]), "=r"(r[3]) : "r"(addr));
}
__device__ __forceinline__ void mma_bf16(float* c, const uint32_t* a, uint32_t b0, uint32_t b1) {
    asm volatile(
        "mma.sync.aligned.m16n8k16.row.col.f32.bf16.bf16.f32 "
        "{%0,%1,%2,%3}, {%4,%5,%6,%7}, {%8,%9}, {%0,%1,%2,%3};"
        : "+f"(c[0]), "+f"(c[1]), "+f"(c[2]), "+f"(c[3])
        : "r"(a[0]), "r"(a[1]), "r"(a[2]), "r"(a[3]), "r"(b0), "r"(b1));
}
// 64B-row swizzle for BK=32 tiles
__device__ __forceinline__ uint32_t swz(int row, int c) {
    return (uint32_t)(row * 64 + ((c ^ ((row >> 1) & 3)) * 16));
}
__device__ __forceinline__ void split_bf16(float v, __nv_bfloat16& hi, __nv_bfloat16& lo) {
    hi = __float2bfloat16(v);
    lo = __float2bfloat16(v - __bfloat162float(hi));
}

// 64x64 tile bf16 GEMM over NIT k-chunks of 32 starting at koff.
// 6-stage cp.async pipeline, 5 groups in flight. blockDim = 256. (R7 proven)
template <int NIT>
__device__ __forceinline__ void tile_mma(const __nv_bfloat16* __restrict__ Ag,
                                         const __nv_bfloat16* __restrict__ Bg,
                                         int bm, int bn, int koff, char* spipe,
                                         float acc[4][4]) {
    uint32_t smb = smem_u32(spipe);
    int tid = threadIdx.x;
    int wid = tid >> 5, lane = tid & 31;
    int wm = wid & 3, wn = wid >> 2;
    int a_r = lane & 15, a_c = lane >> 4;
    int b_r = (lane & 7) | (((lane >> 4) & 1) << 3);
    int b_c = (lane >> 3) & 1;
    int lrow = tid >> 2, lc = tid & 3;
#pragma unroll
    for (int q = 0; q < 4; q++)
#pragma unroll
        for (int j = 0; j < 4; j++) acc[q][j] = 0.f;

    const __nv_bfloat16* Abase = Ag + (size_t)(bm + lrow) * LKP + koff + lc * 8;
    const __nv_bfloat16* Bbase = Bg + (size_t)(bn + lrow) * LKP + koff + lc * 8;

#pragma unroll
    for (int st = 0; st < 5; st++) {
        if (st < NIT) {
            uint32_t ab = smb + st * 8192;
            cp16(ab + swz(lrow, lc), Abase + st * 32);
            cp16(ab + 4096 + swz(lrow, lc), Bbase + st * 32);
        }
        cp_commit();
    }
    for (int kt = 0; kt < NIT; kt++) {
        cp_wait<4>();
        __syncthreads();
        int nx = kt + 5;
        if (nx < NIT) {
            uint32_t ab = smb + (nx % 6) * 8192;
            cp16(ab + swz(lrow, lc), Abase + (size_t)nx * 32);
            cp16(ab + 4096 + swz(lrow, lc), Bbase + (size_t)nx * 32);
        }
        cp_commit();
        uint32_t ab = smb + (kt % 6) * 8192;
        uint32_t bb = ab + 4096;
#pragma unroll
        for (int s = 0; s < 2; s++) {
            uint32_t af[4];
            ldm_x4(af, ab + swz(wm * 16 + a_r, s * 2 + a_c));
#pragma unroll
            for (int jj = 0; jj < 2; jj++) {
                uint32_t bf[4];
                ldm_x4(bf, bb + swz(wn * 32 + jj * 16 + b_r, s * 2 + b_c));
                mma_bf16(acc[2 * jj], af, bf[0], bf[1]);
                mma_bf16(acc[2 * jj + 1], af, bf[2], bf[3]);
            }
        }
        __syncthreads();
    }
}

// ---------------- setup kernels (3 launches before loop) ------------------------
__global__ void zero_all_kernel() {
    size_t stride = (size_t)gridDim.x * blockDim.x;
    size_t id = (size_t)blockIdx.x * blockDim.x + threadIdx.x;
    uint4 z = make_uint4(0, 0, 0, 0);
    uint4* pa = (uint4*)g_Aattn;
    size_t nA = sizeof(g_Aattn) / 16;
    for (size_t i = id; i < nA; i += stride) pa[i] = z;
    uint4* pc = (uint4*)g_Acomb;
    for (size_t i = id; i < nA; i += stride) pc[i] = z;
    uint4* pi = (uint4*)g_Aih;
    size_t nI = sizeof(g_Aih) / 16;
    for (size_t i = id; i < nI; i += stride) pi[i] = z;
    uint4* ps = (uint4*)g_cst;
    size_t nS = sizeof(g_cst) / 16;
    for (size_t i = id; i < nS; i += stride) ps[i] = z;
}

__global__ void setup_x2_kernel(const float* __restrict__ wv) {
    int idx = blockIdx.x * blockDim.x + threadIdx.x;
    const int total = TT * BB * WVV;
    if (idx >= total) return;
    int t = idx / (BB * WVV);
    int r = idx % (BB * WVV);
    int b = r / WVV, w = r % WVV;
    float v = (t == 0) ? 0.f : wv[(size_t)b * TT * WVV + (size_t)(t - 1) * WVV + w];
    __nv_bfloat16 hi, lo;
    split_bf16(v, hi, lo);
    size_t base = ((size_t)t * BB + b) * LKP;
    g_Aattn[base + w] = hi;
    g_Aattn[base + KSEC + w] = hi;
    g_Aattn[base + 2 * KSEC + w] = lo;
    g_Acomb[base + w] = hi;
    g_Acomb[base + KSEC + w] = hi;
    g_Acomb[base + 2 * KSEC + w] = lo;
}

// merged weight prep: wag2 | wcomb2 | wl2 | wp | bl
#define NW0 (768 * KSEC)
#define NW1 (320 * KSEC)
#define NW2 (2048 * KSEC)
#define NW3 (NPAD * HH)
__global__ void setup_weights_kernel(const float* __restrict__ attn_W,
                                     const float* __restrict__ gate_W,
                                     const float* __restrict__ comb_W,
                                     const float* __restrict__ Wih,
                                     const float* __restrict__ Whh,
                                     const float* __restrict__ bih,
                                     const float* __restrict__ bhh,
                                     const float* __restrict__ vw) {
    long idx = (long)blockIdx.x * blockDim.x + threadIdx.x;
    if (idx < 2048) g_bl[idx] = bih[idx] + bhh[idx];
    if (idx < NW0) {
        int n = idx / KSEC, k = idx % KSEC;
        float v = 0.f;
        if (k < XK) {
            if (n < FF) v = attn_W[(size_t)n * XK + k];
            else if (n < NAG && k >= WVV) v = gate_W[(size_t)(n - FF) * HH + (k - WVV)];
        }
        __nv_bfloat16 hi, lo;
        split_bf16(v, hi, lo);
        size_t base = (size_t)n * LKP;
        g_Wag2[base + k] = hi;
        g_Wag2[base + KSEC + k] = lo;
        g_Wag2[base + 2 * KSEC + k] = hi;
        return;
    }
    idx -= NW0;
    if (idx < NW1) {
        int n = idx / KSEC, k = idx % KSEC;
        float v = (n < WVV && k < XK) ? comb_W[(size_t)n * XK + k] : 0.f;
        __nv_bfloat16 hi, lo;
        split_bf16(v, hi, lo);
        size_t base = (size_t)n * LKP;
        g_Wcomb2[base + k] = hi;
        g_Wcomb2[base + KSEC + k] = lo;
        g_Wcomb2[base + 2 * KSEC + k] = hi;
        return;
    }
    idx -= NW1;
    if (idx < NW2) {
        int n = idx / KSEC, k = idx % KSEC;
        float v = 0.f;
        if (k < XK) v = (k < WVV) ? Wih[(size_t)n * WVV + k] : Whh[(size_t)n * HH + (k - WVV)];
        __nv_bfloat16 hi, lo;
        split_bf16(v, hi, lo);
        size_t base = (size_t)n * LKP;
        g_Wl2[base + k] = hi;
        g_Wl2[base + KSEC + k] = lo;
        g_Wl2[base + 2 * KSEC + k] = hi;
        return;
    }
    idx -= NW2;
    if (idx < NW3) {
        int n = idx / HH, k = idx % HH;
        float v = (n < VV) ? vw[(size_t)n * HH + k] : 0.f;
        __nv_bfloat16 hi, lo;
        split_bf16(v, hi, lo);
        size_t base = (size_t)n * KP;
        g_wp[base + k] = hi;
        g_wp[base + HH + k] = lo;
        g_wp[base + 2 * HH + k] = hi;
    }
}

// ---------------- loop kernels (5 launches per step) ----------------------------
// P1: attn+gate logits, split-K x3. grid = 144
__global__ void __launch_bounds__(256, 1) k_p1(const __nv_bfloat16* __restrict__ A) {
    __shared__ __align__(16) char s_pipe[6 * 8192];
    float acc[4][4];
    int job = blockIdx.x;
    int z = job % 3, tile = job / 3;
    int bm = (tile / 12) * 64, bn = (tile % 12) * 64;
    tile_mma<26>(A, g_Wag2, bm, bn, z * KSEC, s_pipe, acc);
    int tid = threadIdx.x, wid = tid >> 5, lane = tid & 31;
    float* dst = g_ag_s + (size_t)z * BB * 768;
    int r0 = bm + (wid & 3) * 16 + (lane >> 2);
    int c0 = bn + (wid >> 2) * 32 + 2 * (lane & 3);
#pragma unroll
    for (int q = 0; q < 4; q++)
#pragma unroll
        for (int h = 0; h < 2; h++) {
            dst[(r0 + 8 * h) * 768 + c0 + q * 8] = acc[q][2 * h];
            dst[(r0 + 8 * h) * 768 + c0 + q * 8 + 1] = acc[q][2 * h + 1];
        }
}

// P2: softmax + gated ctx. grid = BB (one block per b)
__global__ void __launch_bounds__(256, 1)
k_p2(const float* __restrict__ enc, const float* __restrict__ attn_b,
     const float* __restrict__ gate_b, __nv_bfloat16* __restrict__ Acomb_t) {
    __shared__ float s_red[256];
    __shared__ __align__(16) float s_aw[196];
    int b = blockIdx.x;
    int tid = threadIdx.x;
    int wid = tid >> 5, lane = tid & 31;
    const float* p0 = g_ag_s + (size_t)b * 768;
    const float* p1 = p0 + (size_t)BB * 768;
    const float* p2 = p1 + (size_t)BB * 768;
    float v = -3.0e38f;
    if (tid < FF) v = attn_b[tid] + p0[tid] + p1[tid] + p2[tid];
    s_red[tid] = v;
    __syncthreads();
    for (int s = 128; s > 0; s >>= 1) {
        if (tid < s) s_red[tid] = fmaxf(s_red[tid], s_red[tid + s]);
        __syncthreads();
    }
    float mx = s_red[0];
    __syncthreads();
    float e = (tid < FF) ? expf(v - mx) : 0.f;
    s_red[tid] = e;
    __syncthreads();
    for (int s = 128; s > 0; s >>= 1) {
        if (tid < s) s_red[tid] += s_red[tid + s];
        __syncthreads();
    }
    float inv = 1.f / s_red[0];
    __syncthreads();
    if (tid < FF) s_aw[tid] = e * inv;
    __syncthreads();
    const float4* sa4 = (const float4*)s_aw;
    const float4* encb = (const float4*)(enc + (size_t)b * CC * FF);
    size_t cbase = (size_t)b * LKP;
    for (int grp = 0; grp < 8; grp++) {
#pragma unroll
        for (int ci = 0; ci < 8; ci++) {
            int c = wid * 64 + grp * 8 + ci;
            const float4* row = encb + (size_t)c * 49;
            float4 a0 = sa4[lane];
            float4 v0 = row[lane];
            float sum = v0.x * a0.x + v0.y * a0.y + v0.z * a0.z + v0.w * a0.w;
            if (lane < 17) {
                float4 a1 = sa4[lane + 32];
                float4 v1 = row[lane + 32];
                sum += v1.x * a1.x + v1.y * a1.y + v1.z * a1.z + v1.w * a1.w;
            }
#pragma unroll
            for (int o = 16; o > 0; o >>= 1) sum += __shfl_xor_sync(0xffffffffu, sum, o);
            if (lane == 0) {
                float gz = gate_b[c] + p0[FF + c] + p1[FF + c] + p2[FF + c];
                float gamma = 1.f / (1.f + expf(-gz));
                float val = gamma * sum;
                __nv_bfloat16 hi, lo;
                split_bf16(val, hi, lo);
                Acomb_t[cbase + WVV + c] = hi;
                Acomb_t[cbase + KSEC + WVV + c] = hi;
                Acomb_t[cbase + 2 * KSEC + WVV + c] = lo;
            }
        }
    }
}

// P3: comb gemm full-K, relu fused in epilogue -> g_Aih triple. grid = 20
__global__ void __launch_bounds__(256, 1)
k_p3(const __nv_bfloat16* __restrict__ A, const float* __restrict__ comb_b) {
    __shared__ __align__(16) char s_pipe[6 * 8192];
    float acc[4][4];
    int job = blockIdx.x;
    int bm = (job / 5) * 64, bn = (job % 5) * 64;
    tile_mma<78>(A, g_Wcomb2, bm, bn, 0, s_pipe, acc);
    int tid = threadIdx.x, wid = tid >> 5, lane = tid & 31;
    int r0 = bm + (wid & 3) * 16 + (lane >> 2);
    int c0 = bn + (wid >> 2) * 32 + 2 * (lane & 3);
#pragma unroll
    for (int q = 0; q < 4; q++)
#pragma unroll
        for (int h = 0; h < 2; h++) {
            int gm = r0 + 8 * h;
            size_t abase = (size_t)gm * LKP;
#pragma unroll
            for (int u = 0; u < 2; u++) {
                int n = c0 + q * 8 + u;
                if (n < WVV) {
                    float val = fmaxf(acc[q][2 * h + u] + comb_b[n], 0.f);
                    __nv_bfloat16 hi, lo;
                    split_bf16(val, hi, lo);
                    g_Aih[abase + n] = hi;
                    g_Aih[abase + KSEC + n] = hi;
                    g_Aih[abase + 2 * KSEC + n] = lo;
                }
            }
        }
}

// P4: lstm gates gemm full-K -> g_gates. grid = 128
__global__ void __launch_bounds__(256, 1) k_p4() {
    __shared__ __align__(16) char s_pipe[6 * 8192];
    float acc[4][4];
    int job = blockIdx.x;
    int bm = (job / 32) * 64, bn = (job % 32) * 64;
    tile_mma<78>(g_Aih, g_Wl2, bm, bn, 0, s_pipe, acc);
    int tid = threadIdx.x, wid = tid >> 5, lane = tid & 31;
    int r0 = bm + (wid & 3) * 16 + (lane >> 2);
    int c0 = bn + (wid >> 2) * 32 + 2 * (lane & 3);
#pragma unroll
    for (int q = 0; q < 4; q++)
#pragma unroll
        for (int h = 0; h < 2; h++) {
            g_gates[(r0 + 8 * h) * 2048 + c0 + q * 8] = acc[q][2 * h];
            g_gates[(r0 + 8 * h) * 2048 + c0 + q * 8 + 1] = acc[q][2 * h + 1];
        }
}

// P5: LSTM cell elementwise. grid = 512
__global__ void __launch_bounds__(256, 1)
k_p5(int t, __nv_bfloat16* __restrict__ Aattn_next) {
    int idx = blockIdx.x * 256 + threadIdx.x;
    int b = idx >> 9, j = idx & 511;
    const float* gr = g_gates + b * 2048;
    float i_ = gr[j] + g_bl[j];
    float f_ = gr[512 + j] + g_bl[512 + j];
    float g_ = gr[1024 + j] + g_bl[1024 + j];
    float o_ = gr[1536 + j] + g_bl[1536 + j];
    float si = 1.f / (1.f + expf(-i_));
    float sf = 1.f / (1.f + expf(-f_));
    float so = 1.f / (1.f + expf(-o_));
    float cn = sf * g_cst[idx] + si * tanhf(g_);
    float hn = so * tanhf(cn);
    g_cst[idx] = cn;
    __nv_bfloat16 hi, lo;
    split_bf16(hn, hi, lo);
    size_t ib = (size_t)b * LKP + WVV + j;
    g_Aih[ib] = hi;
    g_Aih[ib + KSEC] = hi;
    g_Aih[ib + 2 * KSEC] = lo;
    if (Aattn_next) {
        size_t ab = (size_t)b * LKP + WVV + j;
        Aattn_next[ab] = hi;
        Aattn_next[ab + KSEC] = hi;
        Aattn_next[ab + 2 * KSEC] = lo;
    }
    size_t vb = ((size_t)t * BB + b) * KP;
    g_ap[vb + j] = hi;
    g_ap[vb + HH + j] = hi;
    g_ap[vb + 2 * HH + j] = lo;
}

// ===================== vocab GEMM slice (per-timestep, side stream) =============
#define VBM 128
#define VBN 256
#define NKT (KP / 32)      // 48
#define STAGE_BYTES 24576
#define ASZ 8192
#define NSTAGE 3
#define VSMEM (NSTAGE * STAGE_BYTES)

__device__ __forceinline__ void issue_tile(const __nv_bfloat16* __restrict__ Ag,
                                           const __nv_bfloat16* __restrict__ Bg,
                                           uint32_t smb, int stage, int bm, int bn, int kt) {
    int tid = threadIdx.x;
    uint32_t abase = smb + stage * STAGE_BYTES;
    uint32_t bbase = abase + ASZ;
#pragma unroll
    for (int l = 0; l < 2; l++) {
        int idx = tid + 256 * l;
        int row = idx >> 2, c = idx & 3;
        cp16(abase + swz(row, c), Ag + (size_t)(bm + row) * KP + kt * 32 + c * 8);
    }
#pragma unroll
    for (int l = 0; l < 4; l++) {
        int idx = tid + 256 * l;
        int row = idx >> 2, c = idx & 3;
        cp16(bbase + swz(row, c), Bg + (size_t)(bn + row) * KP + kt * 32 + c * 8);
    }
    cp_commit();
}

__global__ void __launch_bounds__(256, 1)
gemm_vocab_mma(const __nv_bfloat16* __restrict__ Ag, const __nv_bfloat16* __restrict__ Bg,
               const float* __restrict__ bias, float* __restrict__ out, int m0) {
    extern __shared__ char sm[];
    uint32_t smb = smem_u32(sm);
    int tid = threadIdx.x;
    int wid = tid >> 5, lane = tid & 31;
    int wm = wid & 1, wn = wid >> 1;
    int bm = m0 + blockIdx.y * VBM, bn = blockIdx.x * VBN;

    int a_r = lane & 15;
    int a_c = lane >> 4;
    int b_r = (lane & 7) | (((lane >> 4) & 1) << 3);
    int b_c = (lane >> 3) & 1;

    float acc[4][8][4];
#pragma unroll
    for (int i = 0; i < 4; i++)
#pragma unroll
        for (int j = 0; j < 8; j++)
#pragma unroll
            for (int q = 0; q < 4; q++) acc[i][j][q] = 0.f;

    issue_tile(Ag, Bg, smb, 0, bm, bn, 0);
    issue_tile(Ag, Bg, smb, 1, bm, bn, 1);

    for (int kt = 0; kt < NKT; kt++) {
        cp_wait<1>();
        __syncthreads();
        if (kt + 2 < NKT) issue_tile(Ag, Bg, smb, (kt + 2) % NSTAGE, bm, bn, kt + 2);
        uint32_t abase = smb + (kt % NSTAGE) * STAGE_BYTES;
        uint32_t bbase = abase + ASZ;
#pragma unroll
        for (int s = 0; s < 2; s++) {
            uint32_t af[4][4], bf[4][4];
#pragma unroll
            for (int i = 0; i < 4; i++) {
                int row = wm * 64 + i * 16 + a_r;
                ldm_x4(af[i], abase + swz(row, s * 2 + a_c));
            }
#pragma unroll
            for (int jj = 0; jj < 4; jj++) {
                int row = wn * 64 + jj * 16 + b_r;
                ldm_x4(bf[jj], bbase + swz(row, s * 2 + b_c));
            }
#pragma unroll
            for (int i = 0; i < 4; i++)
#pragma unroll
                for (int jj = 0; jj < 4; jj++) {
                    mma_bf16(acc[i][2 * jj], af[i], bf[jj][0], bf[jj][1]);
                    mma_bf16(acc[i][2 * jj + 1], af[i], bf[jj][2], bf[jj][3]);
                }
        }
        __syncthreads();
    }

#pragma unroll
    for (int i = 0; i < 4; i++) {
#pragma unroll
        for (int j = 0; j < 8; j++) {
            int gm0 = bm + wm * 64 + i * 16 + (lane >> 2);
            int gn = bn + wn * 64 + j * 8 + 2 * (lane & 3);
#pragma unroll
            for (int h = 0; h < 2; h++) {
                int gm = gm0 + h * 8;
                int t = gm >> 8, b = gm & 255;
                float* row = out + ((size_t)b * TT + t) * VV;
                float c0 = acc[i][j][2 * h], c1 = acc[i][j][2 * h + 1];
                if (gn < VV) row[gn] = c0 + bias[gn];
                if (gn + 1 < VV) row[gn + 1] = c1 + bias[gn + 1];
            }
        }
    }
}

// ---------------- host launch --------------------------------------------------
extern "C" void kernel_launch(void* const* d_in, const int* in_sizes, int n_in,
                              void* d_out, int out_size) {
    const float* enc     = (const float*)d_in[0];
    const float* wv      = (const float*)d_in[1];
    const float* attn_W  = (const float*)d_in[2];
    const float* attn_b  = (const float*)d_in[3];
    const float* comb_W  = (const float*)d_in[4];
    const float* comb_b  = (const float*)d_in[5];
    const float* gate_W  = (const float*)d_in[6];
    const float* gate_b  = (const float*)d_in[7];
    const float* Wih     = (const float*)d_in[8];
    const float* Whh     = (const float*)d_in[9];
    const float* bih     = (const float*)d_in[10];
    const float* bhh     = (const float*)d_in[11];
    const float* vocab_W = (const float*)d_in[12];
    const float* vocab_b = (const float*)d_in[13];
    float* out = (float*)d_out;

    __nv_bfloat16 *p_Aattn, *p_Acomb, *p_ap, *p_wp;
    cudaGetSymbolAddress((void**)&p_Aattn, g_Aattn);
    cudaGetSymbolAddress((void**)&p_Acomb, g_Acomb);
    cudaGetSymbolAddress((void**)&p_ap, g_ap);
    cudaGetSymbolAddress((void**)&p_wp, g_wp);

    cudaFuncSetAttribute(gemm_vocab_mma, cudaFuncAttributeMaxDynamicSharedMemorySize, VSMEM);

    // side stream + events, created once (host-side resources only)
    static cudaStream_t s_side = nullptr;
    static cudaEvent_t s_ev[TT];
    static cudaEvent_t s_evd;
    if (!s_side) {
        cudaStreamCreateWithFlags(&s_side, cudaStreamNonBlocking);
        for (int t = 0; t < TT; t++)
            cudaEventCreateWithFlags(&s_ev[t], cudaEventDisableTiming);
        cudaEventCreateWithFlags(&s_evd, cudaEventDisableTiming);
    }

    zero_all_kernel<<<1024, 256>>>();
    setup_x2_kernel<<<(TT * BB * WVV + 255) / 256, 256>>>(wv);
    {
        long total = (long)NW0 + NW1 + NW2 + NW3;
        setup_weights_kernel<<<(unsigned)((total + 255) / 256), 256>>>(
            attn_W, gate_W, comb_W, Wih, Whh, bih, bhh, vocab_W);
    }

    for (int t = 0; t < TT; t++) {
        const __nv_bfloat16* Aat = p_Aattn + (size_t)t * BB * LKP;
        __nv_bfloat16* Aco = p_Acomb + (size_t)t * BB * LKP;
        k_p1<<<144, 256>>>(Aat);
        k_p2<<<BB, 256>>>(enc, attn_b, gate_b, Aco);
        k_p3<<<20, 256>>>(Aco, comb_b);
        k_p4<<<128, 256>>>();
        __nv_bfloat16* Anext = (t + 1 < TT) ? (p_Aattn + (size_t)(t + 1) * BB * LKP) : (__nv_bfloat16*)nullptr;
        k_p5<<<512, 256>>>(t, Anext);
        // fork: vocab slice for this timestep on the side stream
        cudaEventRecord(s_ev[t], 0);
        cudaStreamWaitEvent(s_side, s_ev[t], 0);
        gemm_vocab_mma<<<dim3(NPAD / VBN, BB / VBM), 256, VSMEM, s_side>>>(
            p_ap, p_wp, vocab_b, out, t * BB);
    }
    // join side stream back into the main stream
    cudaEventRecord(s_evd, s_side);
    cudaStreamWaitEvent(0, s_evd, 0);
}